// round 7
// baseline (speedup 1.0000x reference)
#include <cuda_runtime.h>
#include <cstdint>

// Problem constants
#define SQ   2048        // sequence length
#define DK   64          // head dim
#define NBH  64          // B*H = 4*16
#define NB   4           // batch
#define TM   16          // query rows per CTA
#define TN   128         // key/value columns per tile
#define NTHREADS 256
#define NTILES (SQ / TN) // 16

// Canonical mask: 1 byte per element, [B][S]. Filled by mask_canon_kernel.
__device__ unsigned char g_mask[NB * SQ];

// ---------------------------------------------------------------------------
// Mask canonicalization: the reference mask is jnp.bool_ (B,1,1,S); the
// harness may materialize it as int32, uint8, or float32. Detect from the
// first 8192 bytes (safe to read under every interpretation) and convert to
// uint8 0/1. Deterministic, allocation-free, graph-capturable.
// ---------------------------------------------------------------------------
__global__ void mask_canon_kernel(const unsigned char* __restrict__ mraw)
{
    __shared__ int flagGT1, flagOff;
    const int tid = threadIdx.x;
    if (tid == 0) { flagGT1 = 0; flagOff = 0; }
    __syncthreads();

    int lGT1 = 0, lOff = 0;
    for (int i = tid; i < NB * SQ; i += NTHREADS) {   // first 8192 bytes only
        unsigned char b = mraw[i];
        if (b > 1)            lGT1 = 1;
        if ((i & 3) && b)     lOff = 1;
    }
    if (lGT1) atomicOr(&flagGT1, 1);
    if (lOff) atomicOr(&flagOff, 1);
    __syncthreads();

    if (flagGT1) {
        // float32 mask (bytes 0x80/0x3F present)
        const float* mf = reinterpret_cast<const float*>(mraw);
        for (int i = tid; i < NB * SQ; i += NTHREADS)
            g_mask[i] = (mf[i] != 0.0f) ? 1 : 0;
    } else if (flagOff) {
        // genuine uint8 bool mask
        for (int i = tid; i < NB * SQ; i += NTHREADS)
            g_mask[i] = mraw[i] ? 1 : 0;
    } else {
        // int32 mask: nonzero bytes only at 4-byte-aligned offsets
        const int* mi = reinterpret_cast<const int*>(mraw);
        for (int i = tid; i < NB * SQ; i += NTHREADS)
            g_mask[i] = (mi[i] != 0) ? 1 : 0;
    }
}

// Shared memory layout (~168.5 KB)
struct Smem {
    float sS[TM][SQ];      // 131072 B : scores -> p = exp(s - m)
    float sKV[DK * TN];    //  32768 B : K tile [d][t] (64x128) OR V tile [t][d] (128x64)
    float sQt[DK][18];     //   4608 B : Q tile transposed, padded stride 18
    float sInv[TM];        // 1/l per row
};

__global__ __launch_bounds__(NTHREADS, 1)
void sdpa_fp32_kernel(const float* __restrict__ q,
                      const float* __restrict__ k,
                      const float* __restrict__ v,
                      float* __restrict__ out_ctx,
                      float* __restrict__ out_attn)
{
    extern __shared__ char smem_raw[];
    Smem& sm = *reinterpret_cast<Smem*>(smem_raw);

    const int bh   = blockIdx.y;           // 0..63
    const int row0 = blockIdx.x * TM;      // query row block
    const int b    = bh >> 4;              // batch index (H=16)
    const int tid  = threadIdx.x;

    const float* __restrict__ Q  = q + (size_t)bh * SQ * DK;
    const float* __restrict__ K  = k + (size_t)bh * DK * SQ;   // [d][t]
    const float* __restrict__ V  = v + (size_t)bh * SQ * DK;
    const unsigned char* __restrict__ Mk = g_mask + (size_t)b * SQ;

    // ---------- Load Q tile (16 x 64) transposed into sQt[d][r] ----------
    {
        int r  = tid & 15;          // 0..15
        int d0 = (tid >> 4) * 4;    // 0,4,...,60
        float4 qv = *reinterpret_cast<const float4*>(Q + (size_t)(row0 + r) * DK + d0);
        sm.sQt[d0 + 0][r] = qv.x;
        sm.sQt[d0 + 1][r] = qv.y;
        sm.sQt[d0 + 2][r] = qv.z;
        sm.sQt[d0 + 3][r] = qv.w;
    }

    // ---------- Phase 1: scores = (Q K) * scale, masked -> sS ----------
    const int cg = tid & 31;   // col group: cols c0 = cg*4
    const int rg = tid >> 5;   // row group: rows r0 = rg*2  (8 warps x 2 rows = 16)
    const int r0 = rg * 2;
    const int c0 = cg * 4;
    const float scale = 0.125f;   // 1/sqrt(64)

    for (int jt = 0; jt < NTILES; ++jt) {
        const int t0 = jt * TN;
        __syncthreads();  // previous tile's consumers done with sKV (covers Q-load on jt=0)
        // load K tile: 64 rows (d) x 128 cols (t), coalesced float4
        #pragma unroll
        for (int i = tid; i < (DK * TN) / 4; i += NTHREADS) {
            int d  = i >> 5;           // 32 float4 per row
            int c4 = (i & 31) * 4;
            *reinterpret_cast<float4*>(&sm.sKV[d * TN + c4]) =
                *reinterpret_cast<const float4*>(K + (size_t)d * SQ + t0 + c4);
        }
        __syncthreads();

        float a00 = 0.f, a01 = 0.f, a02 = 0.f, a03 = 0.f;
        float a10 = 0.f, a11 = 0.f, a12 = 0.f, a13 = 0.f;
        #pragma unroll 8
        for (int d = 0; d < DK; ++d) {
            float2 q2 = *reinterpret_cast<const float2*>(&sm.sQt[d][r0]);  // broadcast in warp
            float4 k4 = *reinterpret_cast<const float4*>(&sm.sKV[d * TN + c0]);
            a00 += q2.x * k4.x;  a01 += q2.x * k4.y;  a02 += q2.x * k4.z;  a03 += q2.x * k4.w;
            a10 += q2.y * k4.x;  a11 += q2.y * k4.y;  a12 += q2.y * k4.z;  a13 += q2.y * k4.w;
        }

        uchar4 mk = *reinterpret_cast<const uchar4*>(Mk + t0 + c0);
        float4 s0, s1;
        s0.x = mk.x ? -1e9f : a00 * scale;   s1.x = mk.x ? -1e9f : a10 * scale;
        s0.y = mk.y ? -1e9f : a01 * scale;   s1.y = mk.y ? -1e9f : a11 * scale;
        s0.z = mk.z ? -1e9f : a02 * scale;   s1.z = mk.z ? -1e9f : a12 * scale;
        s0.w = mk.w ? -1e9f : a03 * scale;   s1.w = mk.w ? -1e9f : a13 * scale;
        *reinterpret_cast<float4*>(&sm.sS[r0    ][t0 + c0]) = s0;
        *reinterpret_cast<float4*>(&sm.sS[r0 + 1][t0 + c0]) = s1;
    }
    __syncthreads();

    // ---------- Phase 2: row softmax stats, p = exp(s - m) in place ----------
    {
        const int warp = tid >> 5, lane = tid & 31;
        #pragma unroll
        for (int rr = 0; rr < 2; ++rr) {
            int r = warp * 2 + rr;
            float m = -3.4e38f;
            for (int i = lane * 4; i < SQ; i += 128) {
                float4 sv = *reinterpret_cast<const float4*>(&sm.sS[r][i]);
                m = fmaxf(m, fmaxf(fmaxf(sv.x, sv.y), fmaxf(sv.z, sv.w)));
            }
            #pragma unroll
            for (int o = 16; o > 0; o >>= 1) m = fmaxf(m, __shfl_xor_sync(0xffffffffu, m, o));

            float l = 0.f;
            for (int i = lane * 4; i < SQ; i += 128) {
                float4 sv = *reinterpret_cast<float4*>(&sm.sS[r][i]);
                sv.x = __expf(sv.x - m);
                sv.y = __expf(sv.y - m);
                sv.z = __expf(sv.z - m);
                sv.w = __expf(sv.w - m);
                l += (sv.x + sv.y) + (sv.z + sv.w);
                *reinterpret_cast<float4*>(&sm.sS[r][i]) = sv;
            }
            #pragma unroll
            for (int o = 16; o > 0; o >>= 1) l += __shfl_xor_sync(0xffffffffu, l, o);
            if (lane == 0) sm.sInv[r] = 1.0f / l;
        }
    }
    __syncthreads();

    // ---------- Phase 2b: write attn = p * inv_l (coalesced float4 stores) ----------
    {
        int r = tid >> 4;                   // 0..15
        float inv = sm.sInv[r];
        float* __restrict__ dst = out_attn + ((size_t)bh * SQ + row0 + r) * SQ;
        for (int i = (tid & 15) * 4; i < SQ; i += 64) {
            float4 p = *reinterpret_cast<const float4*>(&sm.sS[r][i]);
            p.x *= inv; p.y *= inv; p.z *= inv; p.w *= inv;
            *reinterpret_cast<float4*>(&dst[i]) = p;
        }
    }

    // ---------- Phase 3: context = (p @ V) * inv_l ----------
    const int dg  = tid & 31;     // dd0 = dg*2
    const int rg3 = tid >> 5;     // rows rg3*2, rg3*2+1
    const int pr0 = rg3 * 2;
    const int dd0 = dg * 2;
    float b00 = 0.f, b01 = 0.f, b10 = 0.f, b11 = 0.f;

    for (int jt = 0; jt < NTILES; ++jt) {
        __syncthreads();   // previous consumers done with sKV
        // load V tile 128 x 64 (linear copy, coalesced)
        #pragma unroll
        for (int i = tid * 4; i < TN * DK; i += NTHREADS * 4) {
            *reinterpret_cast<float4*>(&sm.sKV[i]) =
                *reinterpret_cast<const float4*>(V + (size_t)jt * TN * DK + i);
        }
        __syncthreads();

        const float* __restrict__ pRow0 = &sm.sS[pr0    ][jt * TN];
        const float* __restrict__ pRow1 = &sm.sS[pr0 + 1][jt * TN];
        #pragma unroll 4
        for (int t = 0; t < TN; ++t) {
            float p0 = pRow0[t];   // broadcast within warp
            float p1 = pRow1[t];
            float2 v2 = *reinterpret_cast<const float2*>(&sm.sKV[t * DK + dd0]);
            b00 += p0 * v2.x;  b01 += p0 * v2.y;
            b10 += p1 * v2.x;  b11 += p1 * v2.y;
        }
    }

    {
        float inv0 = sm.sInv[pr0];
        float inv1 = sm.sInv[pr0 + 1];
        float2 o0; o0.x = b00 * inv0; o0.y = b01 * inv0;
        float2 o1; o1.x = b10 * inv1; o1.y = b11 * inv1;
        float* __restrict__ c0p = out_ctx + ((size_t)bh * SQ + row0 + pr0) * DK + dd0;
        *reinterpret_cast<float2*>(c0p)      = o0;
        *reinterpret_cast<float2*>(c0p + DK) = o1;
    }
}

extern "C" void kernel_launch(void* const* d_in, const int* in_sizes, int n_in,
                              void* d_out, int out_size)
{
    const float* q = (const float*)d_in[0];
    const float* k = (const float*)d_in[1];
    const float* v = (const float*)d_in[2];
    const unsigned char* mraw = (const unsigned char*)d_in[3];

    float* out = (float*)d_out;
    float* out_ctx  = out;                                   // [B,H,S,D]
    float* out_attn = out + (size_t)NBH * SQ * DK;           // [B,H,S,S]

    // Canonicalize mask dtype -> uint8 g_mask (same stream => ordered).
    mask_canon_kernel<<<1, NTHREADS>>>(mraw);

    const int smem_bytes = (int)sizeof(Smem);
    cudaFuncSetAttribute(sdpa_fp32_kernel,
                         cudaFuncAttributeMaxDynamicSharedMemorySize, smem_bytes);

    dim3 grid(SQ / TM, NBH);   // (128, 64) = 8192 CTAs
    sdpa_fp32_kernel<<<grid, NTHREADS, smem_bytes>>>(q, k, v, out_ctx, out_attn);
}